// round 1
// baseline (speedup 1.0000x reference)
#include <cuda_runtime.h>
#include <math.h>

// Problem constants (fixed by the reference)
#define BB    4
#define NQ    2048
#define NKV   4096
#define QDIM  512
#define KVDIM 128
#define NH    8
#define HD    64
#define INNER 512     // NH * HD
#define ATT_SCALE 0.125f   // HD^-0.5

// ---------------------------------------------------------------------------
// Scratch (device globals; no allocation allowed in kernel_launch)
// ---------------------------------------------------------------------------
__device__ float g_Qp[BB * NQ  * INNER];   // 16 MB
__device__ float g_Kp[BB * NKV * INNER];   // 32 MB
__device__ float g_Vp[BB * NKV * INNER];   // 32 MB
__device__ float g_AO[BB * NQ  * INNER];   // 16 MB

// ---------------------------------------------------------------------------
// Generic NT GEMM:  C[M,N] = A[M,K] @ W[N,K]^T (+ bias[N])
// Both operands K-contiguous (row-major), tile 64x64x16, 256 threads, 4x4/thread
// ---------------------------------------------------------------------------
template <bool HAS_BIAS>
__global__ __launch_bounds__(256) void gemm_nt_kernel(
    const float* __restrict__ A, const float* __restrict__ W,
    const float* __restrict__ bias, float* __restrict__ C,
    int M, int N, int K)
{
    __shared__ float As[16][64];   // [k][m]
    __shared__ float Ws[16][64];   // [k][n]

    const int tid = threadIdx.x;
    const int tx = tid & 15;        // n-group
    const int ty = tid >> 4;        // m-group
    const int bm = blockIdx.y * 64;
    const int bn = blockIdx.x * 64;

    // loader mapping: each thread loads one float4 of A and one of W per k-tile
    const int lr = tid >> 2;              // 0..63 (row within tile)
    const int lc = (tid & 3) * 4;         // 0,4,8,12 (k offset)

    float acc[4][4];
#pragma unroll
    for (int i = 0; i < 4; i++)
#pragma unroll
        for (int j = 0; j < 4; j++) acc[i][j] = 0.f;

    for (int k0 = 0; k0 < K; k0 += 16) {
        float4 av = *(const float4*)&A[(size_t)(bm + lr) * K + k0 + lc];
        float4 wv = *(const float4*)&W[(size_t)(bn + lr) * K + k0 + lc];
        As[lc + 0][lr] = av.x; As[lc + 1][lr] = av.y;
        As[lc + 2][lr] = av.z; As[lc + 3][lr] = av.w;
        Ws[lc + 0][lr] = wv.x; Ws[lc + 1][lr] = wv.y;
        Ws[lc + 2][lr] = wv.z; Ws[lc + 3][lr] = wv.w;
        __syncthreads();

#pragma unroll
        for (int kk = 0; kk < 16; kk++) {
            float4 a4 = *(const float4*)&As[kk][ty * 4];
            float4 w4 = *(const float4*)&Ws[kk][tx * 4];
            float a[4] = {a4.x, a4.y, a4.z, a4.w};
            float w[4] = {w4.x, w4.y, w4.z, w4.w};
#pragma unroll
            for (int i = 0; i < 4; i++)
#pragma unroll
                for (int j = 0; j < 4; j++) acc[i][j] += a[i] * w[j];
        }
        __syncthreads();
    }

#pragma unroll
    for (int i = 0; i < 4; i++) {
        const int m = bm + ty * 4 + i;
        const int n = bn + tx * 4;
        float4 o = make_float4(acc[i][0], acc[i][1], acc[i][2], acc[i][3]);
        if (HAS_BIAS) {
            o.x += bias[n + 0]; o.y += bias[n + 1];
            o.z += bias[n + 2]; o.w += bias[n + 3];
        }
        *(float4*)&C[(size_t)m * N + n] = o;
    }
}

// ---------------------------------------------------------------------------
// Flash-attention core. One block = (b, h, 64-row Q tile).
// smem: sQt[64d][64q], sKt[64d][64k], sV[64k][64d], sPt[64k][64q]  (64 KB)
// ---------------------------------------------------------------------------
__device__ __forceinline__ float rmax16(float v) {
    v = fmaxf(v, __shfl_xor_sync(0xffffffffu, v, 1));
    v = fmaxf(v, __shfl_xor_sync(0xffffffffu, v, 2));
    v = fmaxf(v, __shfl_xor_sync(0xffffffffu, v, 4));
    v = fmaxf(v, __shfl_xor_sync(0xffffffffu, v, 8));
    return v;
}
__device__ __forceinline__ float rsum16(float v) {
    v += __shfl_xor_sync(0xffffffffu, v, 1);
    v += __shfl_xor_sync(0xffffffffu, v, 2);
    v += __shfl_xor_sync(0xffffffffu, v, 4);
    v += __shfl_xor_sync(0xffffffffu, v, 8);
    return v;
}

__global__ __launch_bounds__(256) void attn_kernel()
{
    extern __shared__ float sm[];
    float* sQt = sm;                 // d-major Q (pre-scaled)
    float* sKt = sm + 64 * 64;       // d-major K tile
    float* sV  = sm + 2 * 64 * 64;   // k-major V tile
    float* sPt = sm + 3 * 64 * 64;   // k-major P (transposed: [k][q])

    const int qt = blockIdx.x;       // 0..31
    const int h  = blockIdx.y;       // 0..7
    const int b  = blockIdx.z;       // 0..3
    const int tid = threadIdx.x;
    const int tx = tid & 15;         // k / d column group
    const int ty = tid >> 4;         // q row group

    const float* Qbase = g_Qp + (size_t)(b * NQ + qt * 64) * INNER + h * HD;
    const float* Kbase = g_Kp + (size_t)b * NKV * INNER + h * HD;
    const float* Vbase = g_Vp + (size_t)b * NKV * INNER + h * HD;

    // Load Q tile transposed + pre-scale by 1/sqrt(d)
    {
        const int lr = tid >> 2;            // q row
        const int lc = (tid & 3) * 16;      // d offset
#pragma unroll
        for (int u = 0; u < 4; u++) {
            float4 v = *(const float4*)&Qbase[(size_t)lr * INNER + lc + u * 4];
            sQt[(lc + u * 4 + 0) * 64 + lr] = v.x * ATT_SCALE;
            sQt[(lc + u * 4 + 1) * 64 + lr] = v.y * ATT_SCALE;
            sQt[(lc + u * 4 + 2) * 64 + lr] = v.z * ATT_SCALE;
            sQt[(lc + u * 4 + 3) * 64 + lr] = v.w * ATT_SCALE;
        }
    }

    float m_i[4], l_i[4], o[4][4];
#pragma unroll
    for (int i = 0; i < 4; i++) {
        m_i[i] = -INFINITY; l_i[i] = 0.f;
#pragma unroll
        for (int j = 0; j < 4; j++) o[i][j] = 0.f;
    }

    const int lr = tid >> 2;
    const int lc = (tid & 3) * 16;

    for (int it = 0; it < NKV / 64; it++) {
        __syncthreads();   // previous iteration fully consumed sKt/sV/sPt

        // Load K tile (transposed to d-major) and V tile (k-major)
        const float* Krow = Kbase + (size_t)(it * 64 + lr) * INNER;
        const float* Vrow = Vbase + (size_t)(it * 64 + lr) * INNER;
#pragma unroll
        for (int u = 0; u < 4; u++) {
            float4 kv4 = *(const float4*)&Krow[lc + u * 4];
            sKt[(lc + u * 4 + 0) * 64 + lr] = kv4.x;
            sKt[(lc + u * 4 + 1) * 64 + lr] = kv4.y;
            sKt[(lc + u * 4 + 2) * 64 + lr] = kv4.z;
            sKt[(lc + u * 4 + 3) * 64 + lr] = kv4.w;
            *(float4*)&sV[lr * 64 + lc + u * 4] = *(const float4*)&Vrow[lc + u * 4];
        }
        __syncthreads();

        // S = Q K^T (64x64), this thread: q rows ty*4.., k cols tx*4..
        float s[4][4];
#pragma unroll
        for (int i = 0; i < 4; i++)
#pragma unroll
            for (int j = 0; j < 4; j++) s[i][j] = 0.f;

#pragma unroll 8
        for (int d = 0; d < 64; d++) {
            float4 q4 = *(const float4*)&sQt[d * 64 + ty * 4];
            float4 k4 = *(const float4*)&sKt[d * 64 + tx * 4];
            float qv[4] = {q4.x, q4.y, q4.z, q4.w};
            float kv_[4] = {k4.x, k4.y, k4.z, k4.w};
#pragma unroll
            for (int i = 0; i < 4; i++)
#pragma unroll
                for (int j = 0; j < 4; j++) s[i][j] += qv[i] * kv_[j];
        }

        // Online softmax per q row (reduce across the 16 tx lanes)
#pragma unroll
        for (int i = 0; i < 4; i++) {
            float rm = fmaxf(fmaxf(s[i][0], s[i][1]), fmaxf(s[i][2], s[i][3]));
            rm = rmax16(rm);
            float mnew = fmaxf(m_i[i], rm);
            float corr = __expf(m_i[i] - mnew);
            float rs = 0.f;
#pragma unroll
            for (int j = 0; j < 4; j++) {
                s[i][j] = __expf(s[i][j] - mnew);
                rs += s[i][j];
            }
            rs = rsum16(rs);
            l_i[i] = l_i[i] * corr + rs;
            m_i[i] = mnew;
#pragma unroll
            for (int j = 0; j < 4; j++) o[i][j] *= corr;
        }

        // Write P transposed: sPt[k][q]; this thread owns 4 consecutive q rows
#pragma unroll
        for (int j = 0; j < 4; j++) {
            float4 pv = make_float4(s[0][j], s[1][j], s[2][j], s[3][j]);
            *(float4*)&sPt[(tx * 4 + j) * 64 + ty * 4] = pv;
        }
        __syncthreads();

        // O += P V  (inner dim = k)
#pragma unroll 8
        for (int kk = 0; kk < 64; kk++) {
            float4 p4 = *(const float4*)&sPt[kk * 64 + ty * 4];
            float4 v4 = *(const float4*)&sV[kk * 64 + tx * 4];
            float pv[4] = {p4.x, p4.y, p4.z, p4.w};
            float vv[4] = {v4.x, v4.y, v4.z, v4.w};
#pragma unroll
            for (int i = 0; i < 4; i++)
#pragma unroll
                for (int j = 0; j < 4; j++) o[i][j] += pv[i] * vv[j];
        }
    }

    // Epilogue: normalize and write to AO[b, q, h*64 + d]
#pragma unroll
    for (int i = 0; i < 4; i++) {
        float inv = 1.f / l_i[i];
        float4 ov = make_float4(o[i][0] * inv, o[i][1] * inv,
                                o[i][2] * inv, o[i][3] * inv);
        size_t row = (size_t)(b * NQ + qt * 64 + ty * 4 + i);
        *(float4*)&g_AO[row * INNER + h * HD + tx * 4] = ov;
    }
}

// ---------------------------------------------------------------------------
// Launch
// ---------------------------------------------------------------------------
extern "C" void kernel_launch(void* const* d_in, const int* in_sizes, int n_in,
                              void* d_out, int out_size)
{
    const float* q   = (const float*)d_in[0];
    const float* kv  = (const float*)d_in[1];
    const float* w_q = (const float*)d_in[2];
    const float* w_k = (const float*)d_in[3];
    const float* w_v = (const float*)d_in[4];
    const float* w_o = (const float*)d_in[5];
    const float* b_o = (const float*)d_in[6];
    float* out = (float*)d_out;

    float *Qp, *Kp, *Vp, *AO;
    cudaGetSymbolAddress((void**)&Qp, g_Qp);
    cudaGetSymbolAddress((void**)&Kp, g_Kp);
    cudaGetSymbolAddress((void**)&Vp, g_Vp);
    cudaGetSymbolAddress((void**)&AO, g_AO);

    const int MQ = BB * NQ;    // 8192
    const int MK = BB * NKV;   // 16384

    // Q projection: [8192,512] x [512,512]^T
    gemm_nt_kernel<false><<<dim3(INNER / 64, MQ / 64), 256>>>(
        q, w_q, nullptr, Qp, MQ, INNER, QDIM);
    // K projection: [16384,128] x [512,128]^T
    gemm_nt_kernel<false><<<dim3(INNER / 64, MK / 64), 256>>>(
        kv, w_k, nullptr, Kp, MK, INNER, KVDIM);
    // V projection
    gemm_nt_kernel<false><<<dim3(INNER / 64, MK / 64), 256>>>(
        kv, w_v, nullptr, Vp, MK, INNER, KVDIM);

    // Attention core
    cudaFuncSetAttribute(attn_kernel,
                         cudaFuncAttributeMaxDynamicSharedMemorySize, 65536);
    attn_kernel<<<dim3(NQ / 64, NH, BB), 256, 65536>>>();

    // Output projection + bias: [8192,512] x [512,512]^T + b
    gemm_nt_kernel<true><<<dim3(QDIM / 64, MQ / 64), 256>>>(
        AO, w_o, b_o, out, MQ, QDIM, INNER);
}

// round 3
// speedup vs baseline: 2.7857x; 2.7857x over previous
#include <cuda_runtime.h>
#include <math.h>
#include <stdint.h>

// Problem constants (fixed by the reference)
#define BB    4
#define NQ    2048
#define NKV   4096
#define QDIM  512
#define KVDIM 128
#define NH    8
#define HD    64
#define INNER 512
#define ATT_SCALE 0.125f

// ---------------------------------------------------------------------------
// Scratch
// ---------------------------------------------------------------------------
__device__ float g_Qp[BB * NQ  * INNER];
__device__ float g_Kp[BB * NKV * INNER];
__device__ float g_Vp[BB * NKV * INNER];
__device__ float g_AO[BB * NQ  * INNER];

// ---------------------------------------------------------------------------
// Generic NT GEMM (fp32 scalar, proven): C[M,N] = A[M,K] @ W[N,K]^T (+ bias)
// ---------------------------------------------------------------------------
template <bool HAS_BIAS>
__global__ __launch_bounds__(256) void gemm_nt_kernel(
    const float* __restrict__ A, const float* __restrict__ W,
    const float* __restrict__ bias, float* __restrict__ C,
    int M, int N, int K)
{
    __shared__ float As[16][64];
    __shared__ float Ws[16][64];

    const int tid = threadIdx.x;
    const int tx = tid & 15;
    const int ty = tid >> 4;
    const int bm = blockIdx.y * 64;
    const int bn = blockIdx.x * 64;
    const int lr = tid >> 2;
    const int lc = (tid & 3) * 4;

    float acc[4][4];
#pragma unroll
    for (int i = 0; i < 4; i++)
#pragma unroll
        for (int j = 0; j < 4; j++) acc[i][j] = 0.f;

    for (int k0 = 0; k0 < K; k0 += 16) {
        float4 av = *(const float4*)&A[(size_t)(bm + lr) * K + k0 + lc];
        float4 wv = *(const float4*)&W[(size_t)(bn + lr) * K + k0 + lc];
        As[lc + 0][lr] = av.x; As[lc + 1][lr] = av.y;
        As[lc + 2][lr] = av.z; As[lc + 3][lr] = av.w;
        Ws[lc + 0][lr] = wv.x; Ws[lc + 1][lr] = wv.y;
        Ws[lc + 2][lr] = wv.z; Ws[lc + 3][lr] = wv.w;
        __syncthreads();

#pragma unroll
        for (int kk = 0; kk < 16; kk++) {
            float4 a4 = *(const float4*)&As[kk][ty * 4];
            float4 w4 = *(const float4*)&Ws[kk][tx * 4];
            float a[4] = {a4.x, a4.y, a4.z, a4.w};
            float w[4] = {w4.x, w4.y, w4.z, w4.w};
#pragma unroll
            for (int i = 0; i < 4; i++)
#pragma unroll
                for (int j = 0; j < 4; j++) acc[i][j] += a[i] * w[j];
        }
        __syncthreads();
    }

#pragma unroll
    for (int i = 0; i < 4; i++) {
        const int m = bm + ty * 4 + i;
        const int n = bn + tx * 4;
        float4 o = make_float4(acc[i][0], acc[i][1], acc[i][2], acc[i][3]);
        if (HAS_BIAS) {
            o.x += bias[n + 0]; o.y += bias[n + 1];
            o.z += bias[n + 2]; o.w += bias[n + 3];
        }
        *(float4*)&C[(size_t)m * N + n] = o;
    }
}

// ---------------------------------------------------------------------------
// TF32 mma.sync helpers
// ---------------------------------------------------------------------------
__device__ __forceinline__ uint32_t f2tf32(float x) {
    uint32_t r;
    asm("cvt.rna.tf32.f32 %0, %1;" : "=r"(r) : "f"(x));
    return r;
}

__device__ __forceinline__ void mma_tf32(float d[4], const uint32_t a[4],
                                         const uint32_t b[2], const float c[4]) {
    asm volatile(
        "mma.sync.aligned.m16n8k8.row.col.f32.tf32.tf32.f32 "
        "{%0,%1,%2,%3}, {%4,%5,%6,%7}, {%8,%9}, {%10,%11,%12,%13};\n"
        : "=f"(d[0]), "=f"(d[1]), "=f"(d[2]), "=f"(d[3])
        : "r"(a[0]), "r"(a[1]), "r"(a[2]), "r"(a[3]),
          "r"(b[0]), "r"(b[1]),
          "f"(c[0]), "f"(c[1]), "f"(c[2]), "f"(c[3]));
}

// ---------------------------------------------------------------------------
// Flash-attention core, TF32 tensor-core version.
// Block = (64 q rows, head, batch), 128 threads = 4 warps x 16 q rows.
// smem (tf32 bit patterns):
//   sK: [64 keys][68]   (also Q staging)   — B-frag loads bank-free (4g+t)
//   sV: [64 keys][72]                      — B-frag loads bank-free (8t+g)
//   sP: [4 warps][16 q][68]                — A-frag loads bank-free
// ---------------------------------------------------------------------------
#define BQ   64
#define KT   64
#define KSTR 68
#define VSTR 72
#define ATTN_SMEM ((KT * KSTR + KT * VSTR + 4 * 16 * KSTR) * 4)

__global__ __launch_bounds__(128) void attn_mma_kernel()
{
    extern __shared__ uint32_t sm[];
    uint32_t* sK = sm;                       // KT x KSTR
    uint32_t* sV = sm + KT * KSTR;           // KT x VSTR
    uint32_t* sP = sV + KT * VSTR;           // 4 x 16 x KSTR

    const int qt = blockIdx.x;
    const int h  = blockIdx.y;
    const int b  = blockIdx.z;
    const int tid  = threadIdx.x;
    const int lane = tid & 31;
    const int w    = tid >> 5;
    const int g = lane >> 2;     // groupID (0..7)
    const int t = lane & 3;      // threadID in group

    const float* Qb = g_Qp + (size_t)(b * NQ + qt * BQ) * INNER + h * HD;
    const float* Kb = g_Kp + (size_t)b * NKV * INNER + h * HD;
    const float* Vb = g_Vp + (size_t)b * NKV * INNER + h * HD;

    // ---- Stage Q tile into sK (scaled + tf32), then lift fragments ----
    for (int c = tid; c < BQ * 16; c += 128) {
        int row = c >> 4, col = (c & 15) * 4;
        float4 v = *(const float4*)&Qb[(size_t)row * INNER + col];
        uint4 u;
        u.x = f2tf32(v.x * ATT_SCALE); u.y = f2tf32(v.y * ATT_SCALE);
        u.z = f2tf32(v.z * ATT_SCALE); u.w = f2tf32(v.w * ATT_SCALE);
        *(uint4*)&sK[row * KSTR + col] = u;
    }
    __syncthreads();

    uint32_t qa[8][4];
#pragma unroll
    for (int ks = 0; ks < 8; ks++) {
        int col = ks * 8 + t;
        qa[ks][0] = sK[(w * 16 + g    ) * KSTR + col];
        qa[ks][1] = sK[(w * 16 + g + 8) * KSTR + col];
        qa[ks][2] = sK[(w * 16 + g    ) * KSTR + col + 4];
        qa[ks][3] = sK[(w * 16 + g + 8) * KSTR + col + 4];
    }
    __syncthreads();

    float m0 = -INFINITY, m1 = -INFINITY, l0 = 0.f, l1 = 0.f;
    float o[8][4];
#pragma unroll
    for (int db = 0; db < 8; db++)
#pragma unroll
        for (int j = 0; j < 4; j++) o[db][j] = 0.f;

    uint32_t* sPw = sP + w * 16 * KSTR;

    for (int it = 0; it < NKV / KT; it++) {
        // ---- Load K and V tiles (tf32-converted, vectorized smem stores) ----
        for (int c = tid; c < KT * 16; c += 128) {
            int row = c >> 4, col = (c & 15) * 4;
            size_t goff = (size_t)(it * KT + row) * INNER + col;
            float4 kv4 = *(const float4*)&Kb[goff];
            float4 vv4 = *(const float4*)&Vb[goff];
            uint4 uk, uv;
            uk.x = f2tf32(kv4.x); uk.y = f2tf32(kv4.y);
            uk.z = f2tf32(kv4.z); uk.w = f2tf32(kv4.w);
            uv.x = f2tf32(vv4.x); uv.y = f2tf32(vv4.y);
            uv.z = f2tf32(vv4.z); uv.w = f2tf32(vv4.w);
            *(uint4*)&sK[row * KSTR + col] = uk;
            *(uint4*)&sV[row * VSTR + col] = uv;
        }
        __syncthreads();

        // ---- S = Q K^T : 8 key-blocks x 8 d-steps of m16n8k8 ----
        float s[8][4];
#pragma unroll
        for (int nb = 0; nb < 8; nb++)
#pragma unroll
            for (int j = 0; j < 4; j++) s[nb][j] = 0.f;

#pragma unroll
        for (int ks = 0; ks < 8; ks++) {
#pragma unroll
            for (int nb = 0; nb < 8; nb++) {
                uint32_t bb[2];
                bb[0] = sK[(nb * 8 + g) * KSTR + ks * 8 + t];
                bb[1] = sK[(nb * 8 + g) * KSTR + ks * 8 + t + 4];
                mma_tf32(s[nb], qa[ks], bb, s[nb]);
            }
        }

        // ---- Online softmax (rows g and g+8 of this warp's 16) ----
        float rm0 = -INFINITY, rm1 = -INFINITY;
#pragma unroll
        for (int nb = 0; nb < 8; nb++) {
            rm0 = fmaxf(rm0, fmaxf(s[nb][0], s[nb][1]));
            rm1 = fmaxf(rm1, fmaxf(s[nb][2], s[nb][3]));
        }
        rm0 = fmaxf(rm0, __shfl_xor_sync(0xffffffffu, rm0, 1));
        rm0 = fmaxf(rm0, __shfl_xor_sync(0xffffffffu, rm0, 2));
        rm1 = fmaxf(rm1, __shfl_xor_sync(0xffffffffu, rm1, 1));
        rm1 = fmaxf(rm1, __shfl_xor_sync(0xffffffffu, rm1, 2));

        float mn0 = fmaxf(m0, rm0), mn1 = fmaxf(m1, rm1);
        float corr0 = __expf(m0 - mn0), corr1 = __expf(m1 - mn1);
        m0 = mn0; m1 = mn1;

        float rs0 = 0.f, rs1 = 0.f;
#pragma unroll
        for (int nb = 0; nb < 8; nb++) {
            s[nb][0] = __expf(s[nb][0] - m0);
            s[nb][1] = __expf(s[nb][1] - m0);
            s[nb][2] = __expf(s[nb][2] - m1);
            s[nb][3] = __expf(s[nb][3] - m1);
            rs0 += s[nb][0] + s[nb][1];
            rs1 += s[nb][2] + s[nb][3];
        }
        rs0 += __shfl_xor_sync(0xffffffffu, rs0, 1);
        rs0 += __shfl_xor_sync(0xffffffffu, rs0, 2);
        rs1 += __shfl_xor_sync(0xffffffffu, rs1, 1);
        rs1 += __shfl_xor_sync(0xffffffffu, rs1, 2);
        l0 = l0 * corr0 + rs0;
        l1 = l1 * corr1 + rs1;

#pragma unroll
        for (int db = 0; db < 8; db++) {
            o[db][0] *= corr0; o[db][1] *= corr0;
            o[db][2] *= corr1; o[db][3] *= corr1;
        }

        // ---- P (C-layout) -> smem, re-read in A-layout ----
#pragma unroll
        for (int nb = 0; nb < 8; nb++) {
            sPw[(g    ) * KSTR + nb * 8 + 2 * t    ] = f2tf32(s[nb][0]);
            sPw[(g    ) * KSTR + nb * 8 + 2 * t + 1] = f2tf32(s[nb][1]);
            sPw[(g + 8) * KSTR + nb * 8 + 2 * t    ] = f2tf32(s[nb][2]);
            sPw[(g + 8) * KSTR + nb * 8 + 2 * t + 1] = f2tf32(s[nb][3]);
        }
        __syncwarp();

        // ---- O += P V : 8 key-steps x 8 d-blocks ----
#pragma unroll
        for (int ks = 0; ks < 8; ks++) {
            uint32_t pa[4];
            pa[0] = sPw[(g    ) * KSTR + ks * 8 + t];
            pa[1] = sPw[(g + 8) * KSTR + ks * 8 + t];
            pa[2] = sPw[(g    ) * KSTR + ks * 8 + t + 4];
            pa[3] = sPw[(g + 8) * KSTR + ks * 8 + t + 4];
#pragma unroll
            for (int db = 0; db < 8; db++) {
                uint32_t bb[2];
                bb[0] = sV[(ks * 8 + t    ) * VSTR + db * 8 + g];
                bb[1] = sV[(ks * 8 + t + 4) * VSTR + db * 8 + g];
                mma_tf32(o[db], pa, bb, o[db]);
            }
        }
        __syncthreads();
    }

    // ---- Epilogue: normalize, write AO[b, q, h*64 + d] ----
    float inv0 = 1.f / l0, inv1 = 1.f / l1;
    const int q0 = qt * BQ + w * 16 + g;
    const int q1 = q0 + 8;
#pragma unroll
    for (int db = 0; db < 8; db++) {
        float2 r0 = make_float2(o[db][0] * inv0, o[db][1] * inv0);
        float2 r1 = make_float2(o[db][2] * inv1, o[db][3] * inv1);
        *(float2*)&g_AO[(size_t)(b * NQ + q0) * INNER + h * HD + db * 8 + 2 * t] = r0;
        *(float2*)&g_AO[(size_t)(b * NQ + q1) * INNER + h * HD + db * 8 + 2 * t] = r1;
    }
}

// ---------------------------------------------------------------------------
// Launch
// ---------------------------------------------------------------------------
extern "C" void kernel_launch(void* const* d_in, const int* in_sizes, int n_in,
                              void* d_out, int out_size)
{
    const float* q   = (const float*)d_in[0];
    const float* kv  = (const float*)d_in[1];
    const float* w_q = (const float*)d_in[2];
    const float* w_k = (const float*)d_in[3];
    const float* w_v = (const float*)d_in[4];
    const float* w_o = (const float*)d_in[5];
    const float* b_o = (const float*)d_in[6];
    float* out = (float*)d_out;

    float *Qp, *Kp, *Vp, *AO;
    cudaGetSymbolAddress((void**)&Qp, g_Qp);
    cudaGetSymbolAddress((void**)&Kp, g_Kp);
    cudaGetSymbolAddress((void**)&Vp, g_Vp);
    cudaGetSymbolAddress((void**)&AO, g_AO);

    const int MQ = BB * NQ;    // 8192
    const int MK = BB * NKV;   // 16384

    gemm_nt_kernel<false><<<dim3(INNER / 64, MQ / 64), 256>>>(
        q, w_q, nullptr, Qp, MQ, INNER, QDIM);
    gemm_nt_kernel<false><<<dim3(INNER / 64, MK / 64), 256>>>(
        kv, w_k, nullptr, Kp, MK, INNER, KVDIM);
    gemm_nt_kernel<false><<<dim3(INNER / 64, MK / 64), 256>>>(
        kv, w_v, nullptr, Vp, MK, INNER, KVDIM);

    cudaFuncSetAttribute(attn_mma_kernel,
                         cudaFuncAttributeMaxDynamicSharedMemorySize, ATTN_SMEM);
    attn_mma_kernel<<<dim3(NQ / BQ, NH, BB), 128, ATTN_SMEM>>>();

    gemm_nt_kernel<true><<<dim3(QDIM / 64, MQ / 64), 256>>>(
        AO, w_o, b_o, out, MQ, QDIM, INNER);
}

// round 5
// speedup vs baseline: 3.3888x; 1.2165x over previous
#include <cuda_runtime.h>
#include <math.h>
#include <stdint.h>

// Problem constants
#define BB    4
#define NQ    2048
#define NKV   4096
#define QDIM  512
#define KVDIM 128
#define NH    8
#define HD    64
#define INNER 512
#define ATT_SCALE 0.125f

// ---------------------------------------------------------------------------
// Scratch
// ---------------------------------------------------------------------------
__device__ float g_Qp[BB * NQ  * INNER];
__device__ float g_Kp[BB * NKV * INNER];
__device__ float g_Vp[BB * NKV * INNER];
__device__ float g_AO[BB * NQ  * INNER];

// ---------------------------------------------------------------------------
// Helpers
// ---------------------------------------------------------------------------
__device__ __forceinline__ uint32_t smem_u32(const void* p) {
    uint32_t a;
    asm("{ .reg .u64 t; cvta.to.shared.u64 t, %1; cvt.u32.u64 %0, t; }"
        : "=r"(a) : "l"(p));
    return a;
}
__device__ __forceinline__ void cp16(uint32_t dst, const void* src) {
    asm volatile("cp.async.cg.shared.global [%0], [%1], 16;\n"
                 :: "r"(dst), "l"(src));
}
#define CP_COMMIT() asm volatile("cp.async.commit_group;\n")
#define CP_WAIT1()  asm volatile("cp.async.wait_group 1;\n")
#define CP_WAIT0()  asm volatile("cp.async.wait_group 0;\n")

// RNA (round-to-nearest) fp32 -> tf32: unbiased, REQUIRED for accuracy.
__device__ __forceinline__ uint32_t f2tf32(float x) {
    uint32_t r;
    asm("cvt.rna.tf32.f32 %0, %1;" : "=r"(r) : "f"(x));
    return r;
}
__device__ __forceinline__ uint32_t u2tf32(uint32_t u) {
    uint32_t r;
    asm("cvt.rna.tf32.f32 %0, %1;" : "=r"(r) : "f"(__uint_as_float(u)));
    return r;
}
__device__ __forceinline__ void mma_tf32(float d[4], const uint32_t a[4],
                                         const uint32_t b[2], const float c[4]) {
    asm volatile(
        "mma.sync.aligned.m16n8k8.row.col.f32.tf32.tf32.f32 "
        "{%0,%1,%2,%3}, {%4,%5,%6,%7}, {%8,%9}, {%10,%11,%12,%13};\n"
        : "=f"(d[0]), "=f"(d[1]), "=f"(d[2]), "=f"(d[3])
        : "r"(a[0]), "r"(a[1]), "r"(a[2]), "r"(a[3]),
          "r"(b[0]), "r"(b[1]),
          "f"(c[0]), "f"(c[1]), "f"(c[2]), "f"(c[3]));
}

// ---------------------------------------------------------------------------
// TF32 NT GEMM: C[M,N] = A[M,K] @ W[N,K]^T (+ bias)
// Tile 128x64x32, 256 threads (8 warps x 16 rows), cp.async double-buffered.
// RNA tf32 conversion at fragment load.
// ---------------------------------------------------------------------------
#define GBM 128
#define GBN 64
#define GBK 32
#define GSTR 36
#define GEMM_SMEM ((2*GBM*GSTR + 2*GBN*GSTR)*4)

template <bool HAS_BIAS>
__global__ __launch_bounds__(256) void gemm_tf32_kernel(
    const float* __restrict__ A, const float* __restrict__ W,
    const float* __restrict__ bias, float* __restrict__ C,
    int M, int N, int K)
{
    extern __shared__ uint32_t gsm[];
    uint32_t* sA = gsm;                   // 2 x 128 x 36
    uint32_t* sW = gsm + 2*GBM*GSTR;      // 2 x 64 x 36
    const uint32_t sA_u = smem_u32(sA);
    const uint32_t sW_u = smem_u32(sW);

    const int tid = threadIdx.x;
    const int lane = tid & 31, w = tid >> 5;
    const int g = lane >> 2, t = lane & 3;
    const int bm = blockIdx.y * GBM, bn = blockIdx.x * GBN;
    const int NIT = K / GBK;

    float acc[8][4];
#pragma unroll
    for (int nb = 0; nb < 8; nb++)
#pragma unroll
        for (int j = 0; j < 4; j++) acc[nb][j] = 0.f;

    // prologue load (tile 0, buf 0)
    {
#pragma unroll
        for (int i = 0; i < 4; i++) {
            int idx = tid + i*256, row = idx >> 3, c = idx & 7;
            cp16(sA_u + (row*GSTR + c*4)*4, A + (size_t)(bm + row)*K + c*4);
        }
#pragma unroll
        for (int i = 0; i < 2; i++) {
            int idx = tid + i*256, row = idx >> 3, c = idx & 7;
            cp16(sW_u + (row*GSTR + c*4)*4, W + (size_t)(bn + row)*K + c*4);
        }
        CP_COMMIT();
    }

    for (int it = 0; it < NIT; it++) {
        const int buf = it & 1;
        if (it + 1 < NIT) {
            const int k0 = (it + 1) * GBK, nb_ = (buf ^ 1);
#pragma unroll
            for (int i = 0; i < 4; i++) {
                int idx = tid + i*256, row = idx >> 3, c = idx & 7;
                cp16(sA_u + (nb_*GBM*GSTR + row*GSTR + c*4)*4,
                     A + (size_t)(bm + row)*K + k0 + c*4);
            }
#pragma unroll
            for (int i = 0; i < 2; i++) {
                int idx = tid + i*256, row = idx >> 3, c = idx & 7;
                cp16(sW_u + (nb_*GBN*GSTR + row*GSTR + c*4)*4,
                     W + (size_t)(bn + row)*K + k0 + c*4);
            }
            CP_COMMIT();
            CP_WAIT1();
        } else {
            CP_WAIT0();
        }
        __syncthreads();

        const uint32_t* tA = sA + buf*GBM*GSTR;
        const uint32_t* tW = sW + buf*GBN*GSTR;
#pragma unroll
        for (int ks = 0; ks < 4; ks++) {
            const int col = ks*8 + t;
            uint32_t a[4];
            a[0] = u2tf32(tA[(w*16 + g    )*GSTR + col]);
            a[1] = u2tf32(tA[(w*16 + g + 8)*GSTR + col]);
            a[2] = u2tf32(tA[(w*16 + g    )*GSTR + col + 4]);
            a[3] = u2tf32(tA[(w*16 + g + 8)*GSTR + col + 4]);
#pragma unroll
            for (int nb = 0; nb < 8; nb++) {
                uint32_t bfr[2];
                bfr[0] = u2tf32(tW[(nb*8 + g)*GSTR + col]);
                bfr[1] = u2tf32(tW[(nb*8 + g)*GSTR + col + 4]);
                mma_tf32(acc[nb], a, bfr, acc[nb]);
            }
        }
        __syncthreads();
    }

    const int r0 = bm + w*16 + g, r1 = r0 + 8;
#pragma unroll
    for (int nb = 0; nb < 8; nb++) {
        const int col = bn + nb*8 + 2*t;
        float2 v0 = make_float2(acc[nb][0], acc[nb][1]);
        float2 v1 = make_float2(acc[nb][2], acc[nb][3]);
        if (HAS_BIAS) {
            float b0 = bias[col], b1 = bias[col + 1];
            v0.x += b0; v0.y += b1; v1.x += b0; v1.y += b1;
        }
        *(float2*)&C[(size_t)r0*N + col] = v0;
        *(float2*)&C[(size_t)r1*N + col] = v1;
    }
}

// ---------------------------------------------------------------------------
// Flash-attention core, TF32 MMA, cp.async double-buffered K/V.
// Block = (128 q rows, head, batch), 256 threads = 8 warps x 16 q rows.
// RNA conversion: Q at staging, K/V at fragment load, P at smem store.
// ---------------------------------------------------------------------------
#define BQ   128
#define KT   64
#define KSTR 68
#define VSTR 72
#define NITA (NKV / KT)
#define ATTN_SMEM ((2*KT*KSTR + 2*KT*VSTR + BQ*KSTR)*4)

__global__ __launch_bounds__(256) void attn_mma_kernel()
{
    extern __shared__ uint32_t sm[];
    uint32_t* sK = sm;                      // 2 x 64 x 68 (raw fp32 bits)
    uint32_t* sV = sm + 2*KT*KSTR;          // 2 x 64 x 72 (raw fp32 bits)
    uint32_t* sP = sV + 2*KT*VSTR;          // 128 x 68
    const uint32_t sK_u = smem_u32(sK);
    const uint32_t sV_u = smem_u32(sV);

    const int qt = blockIdx.x, h = blockIdx.y, b = blockIdx.z;
    const int tid = threadIdx.x, lane = tid & 31, w = tid >> 5;
    const int g = lane >> 2, t = lane & 3;

    const float* Qb = g_Qp + (size_t)(b*NQ + qt*BQ)*INNER + h*HD;
    const float* Kb = g_Kp + (size_t)b*NKV*INNER + h*HD;
    const float* Vb = g_Vp + (size_t)b*NKV*INNER + h*HD;

    // ---- issue first K/V tile (overlaps with Q staging) ----
#pragma unroll
    for (int i = 0; i < 4; i++) {
        int idx = tid + i*256, row = idx >> 4, c = idx & 15;
        size_t goff = (size_t)row*INNER + c*4;
        cp16(sK_u + (row*KSTR + c*4)*4, Kb + goff);
        cp16(sV_u + (row*VSTR + c*4)*4, Vb + goff);
    }
    CP_COMMIT();

    // ---- stage Q (scaled, RNA tf32) into sP, lift fragments ----
    for (int cidx = tid; cidx < BQ*16; cidx += 256) {
        int row = cidx >> 4, col = (cidx & 15)*4;
        float4 v = *(const float4*)&Qb[(size_t)row*INNER + col];
        uint4 u;
        u.x = f2tf32(v.x * ATT_SCALE); u.y = f2tf32(v.y * ATT_SCALE);
        u.z = f2tf32(v.z * ATT_SCALE); u.w = f2tf32(v.w * ATT_SCALE);
        *(uint4*)&sP[row*KSTR + col] = u;
    }
    __syncthreads();

    uint32_t qa[8][4];
#pragma unroll
    for (int ks = 0; ks < 8; ks++) {
        const int col = ks*8 + t;
        qa[ks][0] = sP[(w*16 + g    )*KSTR + col];
        qa[ks][1] = sP[(w*16 + g + 8)*KSTR + col];
        qa[ks][2] = sP[(w*16 + g    )*KSTR + col + 4];
        qa[ks][3] = sP[(w*16 + g + 8)*KSTR + col + 4];
    }
    __syncthreads();

    float m0 = -INFINITY, m1 = -INFINITY, l0 = 0.f, l1 = 0.f;
    float o[8][4];
#pragma unroll
    for (int db = 0; db < 8; db++)
#pragma unroll
        for (int j = 0; j < 4; j++) o[db][j] = 0.f;

    uint32_t* sPw = sP + (w*16)*KSTR;

    for (int it = 0; it < NITA; it++) {
        const int buf = it & 1;
        if (it + 1 < NITA) {
            const int nbuf = buf ^ 1;
#pragma unroll
            for (int i = 0; i < 4; i++) {
                int idx = tid + i*256, row = idx >> 4, c = idx & 15;
                size_t goff = (size_t)((it + 1)*KT + row)*INNER + c*4;
                cp16(sK_u + (nbuf*KT*KSTR + row*KSTR + c*4)*4, Kb + goff);
                cp16(sV_u + (nbuf*KT*VSTR + row*VSTR + c*4)*4, Vb + goff);
            }
            CP_COMMIT();
            CP_WAIT1();
        } else {
            CP_WAIT0();
        }
        __syncthreads();

        const uint32_t* tK = sK + buf*KT*KSTR;
        const uint32_t* tV = sV + buf*KT*VSTR;

        // ---- S = Q K^T (K fragments RNA-converted at load) ----
        float s[8][4];
#pragma unroll
        for (int nb = 0; nb < 8; nb++)
#pragma unroll
            for (int j = 0; j < 4; j++) s[nb][j] = 0.f;

#pragma unroll
        for (int ks = 0; ks < 8; ks++) {
            const int col = ks*8 + t;
#pragma unroll
            for (int nb = 0; nb < 8; nb++) {
                uint32_t bfr[2];
                bfr[0] = u2tf32(tK[(nb*8 + g)*KSTR + col]);
                bfr[1] = u2tf32(tK[(nb*8 + g)*KSTR + col + 4]);
                mma_tf32(s[nb], qa[ks], bfr, s[nb]);
            }
        }

        // ---- online softmax ----
        float rm0 = -INFINITY, rm1 = -INFINITY;
#pragma unroll
        for (int nb = 0; nb < 8; nb++) {
            rm0 = fmaxf(rm0, fmaxf(s[nb][0], s[nb][1]));
            rm1 = fmaxf(rm1, fmaxf(s[nb][2], s[nb][3]));
        }
        rm0 = fmaxf(rm0, __shfl_xor_sync(0xffffffffu, rm0, 1));
        rm0 = fmaxf(rm0, __shfl_xor_sync(0xffffffffu, rm0, 2));
        rm1 = fmaxf(rm1, __shfl_xor_sync(0xffffffffu, rm1, 1));
        rm1 = fmaxf(rm1, __shfl_xor_sync(0xffffffffu, rm1, 2));

        float mn0 = fmaxf(m0, rm0), mn1 = fmaxf(m1, rm1);
        float corr0 = __expf(m0 - mn0), corr1 = __expf(m1 - mn1);
        m0 = mn0; m1 = mn1;

        float rs0 = 0.f, rs1 = 0.f;
#pragma unroll
        for (int nb = 0; nb < 8; nb++) {
            s[nb][0] = __expf(s[nb][0] - m0);
            s[nb][1] = __expf(s[nb][1] - m0);
            s[nb][2] = __expf(s[nb][2] - m1);
            s[nb][3] = __expf(s[nb][3] - m1);
            rs0 += s[nb][0] + s[nb][1];
            rs1 += s[nb][2] + s[nb][3];
        }
        rs0 += __shfl_xor_sync(0xffffffffu, rs0, 1);
        rs0 += __shfl_xor_sync(0xffffffffu, rs0, 2);
        rs1 += __shfl_xor_sync(0xffffffffu, rs1, 1);
        rs1 += __shfl_xor_sync(0xffffffffu, rs1, 2);
        l0 = l0 * corr0 + rs0;
        l1 = l1 * corr1 + rs1;

#pragma unroll
        for (int db = 0; db < 8; db++) {
            o[db][0] *= corr0; o[db][1] *= corr0;
            o[db][2] *= corr1; o[db][3] *= corr1;
        }

        // ---- P -> smem (RNA tf32), re-read in A-layout ----
#pragma unroll
        for (int nb = 0; nb < 8; nb++) {
            sPw[(g    )*KSTR + nb*8 + 2*t    ] = f2tf32(s[nb][0]);
            sPw[(g    )*KSTR + nb*8 + 2*t + 1] = f2tf32(s[nb][1]);
            sPw[(g + 8)*KSTR + nb*8 + 2*t    ] = f2tf32(s[nb][2]);
            sPw[(g + 8)*KSTR + nb*8 + 2*t + 1] = f2tf32(s[nb][3]);
        }
        __syncwarp();

        // ---- O += P V (V fragments RNA-converted at load) ----
#pragma unroll
        for (int ks = 0; ks < 8; ks++) {
            uint32_t pa[4];
            pa[0] = sPw[(g    )*KSTR + ks*8 + t];
            pa[1] = sPw[(g + 8)*KSTR + ks*8 + t];
            pa[2] = sPw[(g    )*KSTR + ks*8 + t + 4];
            pa[3] = sPw[(g + 8)*KSTR + ks*8 + t + 4];
#pragma unroll
            for (int db = 0; db < 8; db++) {
                uint32_t bfr[2];
                bfr[0] = u2tf32(tV[(ks*8 + t    )*VSTR + db*8 + g]);
                bfr[1] = u2tf32(tV[(ks*8 + t + 4)*VSTR + db*8 + g]);
                mma_tf32(o[db], pa, bfr, o[db]);
            }
        }
        __syncthreads();
    }

    // ---- epilogue ----
    const float inv0 = 1.f / l0, inv1 = 1.f / l1;
    const int q0 = qt*BQ + w*16 + g, q1 = q0 + 8;
#pragma unroll
    for (int db = 0; db < 8; db++) {
        float2 r0 = make_float2(o[db][0]*inv0, o[db][1]*inv0);
        float2 r1 = make_float2(o[db][2]*inv1, o[db][3]*inv1);
        *(float2*)&g_AO[(size_t)(b*NQ + q0)*INNER + h*HD + db*8 + 2*t] = r0;
        *(float2*)&g_AO[(size_t)(b*NQ + q1)*INNER + h*HD + db*8 + 2*t] = r1;
    }
}

// ---------------------------------------------------------------------------
// Launch
// ---------------------------------------------------------------------------
extern "C" void kernel_launch(void* const* d_in, const int* in_sizes, int n_in,
                              void* d_out, int out_size)
{
    const float* q   = (const float*)d_in[0];
    const float* kv  = (const float*)d_in[1];
    const float* w_q = (const float*)d_in[2];
    const float* w_k = (const float*)d_in[3];
    const float* w_v = (const float*)d_in[4];
    const float* w_o = (const float*)d_in[5];
    const float* b_o = (const float*)d_in[6];
    float* out = (float*)d_out;

    float *Qp, *Kp, *Vp, *AO;
    cudaGetSymbolAddress((void**)&Qp, g_Qp);
    cudaGetSymbolAddress((void**)&Kp, g_Kp);
    cudaGetSymbolAddress((void**)&Vp, g_Vp);
    cudaGetSymbolAddress((void**)&AO, g_AO);

    const int MQ = BB * NQ;    // 8192
    const int MK = BB * NKV;   // 16384

    cudaFuncSetAttribute(gemm_tf32_kernel<false>,
                         cudaFuncAttributeMaxDynamicSharedMemorySize, GEMM_SMEM);
    cudaFuncSetAttribute(gemm_tf32_kernel<true>,
                         cudaFuncAttributeMaxDynamicSharedMemorySize, GEMM_SMEM);
    cudaFuncSetAttribute(attn_mma_kernel,
                         cudaFuncAttributeMaxDynamicSharedMemorySize, ATTN_SMEM);

    gemm_tf32_kernel<false><<<dim3(INNER/GBN, MQ/GBM), 256, GEMM_SMEM>>>(
        q, w_q, nullptr, Qp, MQ, INNER, QDIM);
    gemm_tf32_kernel<false><<<dim3(INNER/GBN, MK/GBM), 256, GEMM_SMEM>>>(
        kv, w_k, nullptr, Kp, MK, INNER, KVDIM);
    gemm_tf32_kernel<false><<<dim3(INNER/GBN, MK/GBM), 256, GEMM_SMEM>>>(
        kv, w_v, nullptr, Vp, MK, INNER, KVDIM);

    attn_mma_kernel<<<dim3(NQ/BQ, NH, BB), 256, ATTN_SMEM>>>();

    gemm_tf32_kernel<true><<<dim3(QDIM/GBN, MQ/GBM), 256, GEMM_SMEM>>>(
        AO, w_o, b_o, out, MQ, QDIM, INNER);
}

// round 6
// speedup vs baseline: 4.1346x; 1.2201x over previous
#include <cuda_runtime.h>
#include <math.h>
#include <stdint.h>

// Problem constants
#define BB    4
#define NQ    2048
#define NKV   4096
#define QDIM  512
#define KVDIM 128
#define NH    8
#define HD    64
#define INNER 512
// attention scale folded with log2(e): 0.125 * 1.4426950408889634
#define Q_PRESCALE 0.18033688011112042f

// ---------------------------------------------------------------------------
// Scratch
// ---------------------------------------------------------------------------
__device__ float g_Qp[BB * NQ  * INNER];
__device__ float g_Kp[BB * NKV * INNER];
__device__ float g_Vp[BB * NKV * INNER];
__device__ float g_AO[BB * NQ  * INNER];

// ---------------------------------------------------------------------------
// Helpers
// ---------------------------------------------------------------------------
__device__ __forceinline__ uint32_t smem_u32(const void* p) {
    uint32_t a;
    asm("{ .reg .u64 t; cvta.to.shared.u64 t, %1; cvt.u32.u64 %0, t; }"
        : "=r"(a) : "l"(p));
    return a;
}
__device__ __forceinline__ void cp16(uint32_t dst, const void* src) {
    asm volatile("cp.async.cg.shared.global [%0], [%1], 16;\n"
                 :: "r"(dst), "l"(src));
}
#define CP_COMMIT() asm volatile("cp.async.commit_group;\n")
#define CP_WAIT1()  asm volatile("cp.async.wait_group 1;\n")
#define CP_WAIT0()  asm volatile("cp.async.wait_group 0;\n")

// RNA fp32 -> tf32 (low 13 bits zeroed; raw-feeding the result to MMA is exact)
__device__ __forceinline__ uint32_t f2tf32(float x) {
    uint32_t r;
    asm("cvt.rna.tf32.f32 %0, %1;" : "=r"(r) : "f"(x));
    return r;
}
__device__ __forceinline__ uint32_t u2tf32(uint32_t u) {
    uint32_t r;
    asm("cvt.rna.tf32.f32 %0, %1;" : "=r"(r) : "f"(__uint_as_float(u)));
    return r;
}
__device__ __forceinline__ float ex2(float x) {
    float r;
    asm("ex2.approx.f32 %0, %1;" : "=f"(r) : "f"(x));
    return r;
}
__device__ __forceinline__ void mma_tf32(float d[4], const uint32_t a[4],
                                         const uint32_t b[2], const float c[4]) {
    asm volatile(
        "mma.sync.aligned.m16n8k8.row.col.f32.tf32.tf32.f32 "
        "{%0,%1,%2,%3}, {%4,%5,%6,%7}, {%8,%9}, {%10,%11,%12,%13};\n"
        : "=f"(d[0]), "=f"(d[1]), "=f"(d[2]), "=f"(d[3])
        : "r"(a[0]), "r"(a[1]), "r"(a[2]), "r"(a[3]),
          "r"(b[0]), "r"(b[1]),
          "f"(c[0]), "f"(c[1]), "f"(c[2]), "f"(c[3]));
}

// ---------------------------------------------------------------------------
// TF32 NT GEMM: C[M,N] = scale * (A[M,K] @ W[N,K]^T) (+ bias)
// ROUND_OUT: epilogue RNA-rounds outputs to tf32 (consumer feeds raw bits).
// ---------------------------------------------------------------------------
#define GBM 128
#define GBN 64
#define GBK 32
#define GSTR 36
#define GEMM_SMEM ((2*GBM*GSTR + 2*GBN*GSTR)*4)

template <bool HAS_BIAS, bool ROUND_OUT>
__global__ __launch_bounds__(256) void gemm_tf32_kernel(
    const float* __restrict__ A, const float* __restrict__ W,
    const float* __restrict__ bias, float* __restrict__ C,
    int M, int N, int K, float scale)
{
    extern __shared__ uint32_t gsm[];
    uint32_t* sA = gsm;                   // 2 x 128 x 36
    uint32_t* sW = gsm + 2*GBM*GSTR;      // 2 x 64 x 36
    const uint32_t sA_u = smem_u32(sA);
    const uint32_t sW_u = smem_u32(sW);

    const int tid = threadIdx.x;
    const int lane = tid & 31, w = tid >> 5;
    const int g = lane >> 2, t = lane & 3;
    const int bm = blockIdx.y * GBM, bn = blockIdx.x * GBN;
    const int NIT = K / GBK;

    float acc[8][4];
#pragma unroll
    for (int nb = 0; nb < 8; nb++)
#pragma unroll
        for (int j = 0; j < 4; j++) acc[nb][j] = 0.f;

    // prologue load (tile 0, buf 0)
    {
#pragma unroll
        for (int i = 0; i < 4; i++) {
            int idx = tid + i*256, row = idx >> 3, c = idx & 7;
            cp16(sA_u + (row*GSTR + c*4)*4, A + (size_t)(bm + row)*K + c*4);
        }
#pragma unroll
        for (int i = 0; i < 2; i++) {
            int idx = tid + i*256, row = idx >> 3, c = idx & 7;
            cp16(sW_u + (row*GSTR + c*4)*4, W + (size_t)(bn + row)*K + c*4);
        }
        CP_COMMIT();
    }

    for (int it = 0; it < NIT; it++) {
        const int buf = it & 1;
        if (it + 1 < NIT) {
            const int k0 = (it + 1) * GBK, nb_ = (buf ^ 1);
#pragma unroll
            for (int i = 0; i < 4; i++) {
                int idx = tid + i*256, row = idx >> 3, c = idx & 7;
                cp16(sA_u + (nb_*GBM*GSTR + row*GSTR + c*4)*4,
                     A + (size_t)(bm + row)*K + k0 + c*4);
            }
#pragma unroll
            for (int i = 0; i < 2; i++) {
                int idx = tid + i*256, row = idx >> 3, c = idx & 7;
                cp16(sW_u + (nb_*GBN*GSTR + row*GSTR + c*4)*4,
                     W + (size_t)(bn + row)*K + k0 + c*4);
            }
            CP_COMMIT();
            CP_WAIT1();
        } else {
            CP_WAIT0();
        }
        __syncthreads();

        const uint32_t* tA = sA + buf*GBM*GSTR;
        const uint32_t* tW = sW + buf*GBN*GSTR;
#pragma unroll
        for (int ks = 0; ks < 4; ks++) {
            const int col = ks*8 + t;
            uint32_t a[4];
            a[0] = u2tf32(tA[(w*16 + g    )*GSTR + col]);
            a[1] = u2tf32(tA[(w*16 + g + 8)*GSTR + col]);
            a[2] = u2tf32(tA[(w*16 + g    )*GSTR + col + 4]);
            a[3] = u2tf32(tA[(w*16 + g + 8)*GSTR + col + 4]);
#pragma unroll
            for (int nb = 0; nb < 8; nb++) {
                uint32_t bfr[2];
                bfr[0] = u2tf32(tW[(nb*8 + g)*GSTR + col]);
                bfr[1] = u2tf32(tW[(nb*8 + g)*GSTR + col + 4]);
                mma_tf32(acc[nb], a, bfr, acc[nb]);
            }
        }
        __syncthreads();
    }

    const int r0 = bm + w*16 + g, r1 = r0 + 8;
#pragma unroll
    for (int nb = 0; nb < 8; nb++) {
        const int col = bn + nb*8 + 2*t;
        float v00 = acc[nb][0]*scale, v01 = acc[nb][1]*scale;
        float v10 = acc[nb][2]*scale, v11 = acc[nb][3]*scale;
        if (HAS_BIAS) {
            float b0 = bias[col], b1 = bias[col + 1];
            v00 += b0; v01 += b1; v10 += b0; v11 += b1;
        }
        float2 o0, o1;
        if (ROUND_OUT) {
            o0 = make_float2(__uint_as_float(f2tf32(v00)), __uint_as_float(f2tf32(v01)));
            o1 = make_float2(__uint_as_float(f2tf32(v10)), __uint_as_float(f2tf32(v11)));
        } else {
            o0 = make_float2(v00, v01);
            o1 = make_float2(v10, v11);
        }
        *(float2*)&C[(size_t)r0*N + col] = o0;
        *(float2*)&C[(size_t)r1*N + col] = o1;
    }
}

// ---------------------------------------------------------------------------
// Flash-attention core. All MMA operands pre-rounded to tf32 by producers;
// zero conversions in the hot loops. Softmax in exp2 domain (scale folded
// into Q projection).
// Block = (128 q rows, head, batch), 256 threads = 8 warps x 16 q rows.
// ---------------------------------------------------------------------------
#define BQ   128
#define KT   64
#define KSTR 68
#define VSTR 72
#define NITA (NKV / KT)
#define ATTN_SMEM ((2*KT*KSTR + 2*KT*VSTR + BQ*KSTR)*4)

__global__ __launch_bounds__(256) void attn_mma_kernel()
{
    extern __shared__ uint32_t sm[];
    uint32_t* sK = sm;                      // 2 x 64 x 68
    uint32_t* sV = sm + 2*KT*KSTR;          // 2 x 64 x 72
    uint32_t* sP = sV + 2*KT*VSTR;          // 128 x 68 (Q staging, then P)
    const uint32_t sK_u = smem_u32(sK);
    const uint32_t sV_u = smem_u32(sV);
    const uint32_t sP_u = smem_u32(sP);

    const int qt = blockIdx.x, h = blockIdx.y, b = blockIdx.z;
    const int tid = threadIdx.x, lane = tid & 31, w = tid >> 5;
    const int g = lane >> 2, t = lane & 3;

    const float* Qb = g_Qp + (size_t)(b*NQ + qt*BQ)*INNER + h*HD;
    const float* Kb = g_Kp + (size_t)b*NKV*INNER + h*HD;
    const float* Vb = g_Vp + (size_t)b*NKV*INNER + h*HD;

    // ---- stage Q via cp.async (group 0) ----
#pragma unroll
    for (int i = 0; i < 8; i++) {
        int idx = tid + i*256, row = idx >> 4, c = idx & 15;
        cp16(sP_u + (row*KSTR + c*4)*4, Qb + (size_t)row*INNER + c*4);
    }
    CP_COMMIT();

    // ---- first K/V tile (group 1) ----
#pragma unroll
    for (int i = 0; i < 4; i++) {
        int idx = tid + i*256, row = idx >> 4, c = idx & 15;
        size_t goff = (size_t)row*INNER + c*4;
        cp16(sK_u + (row*KSTR + c*4)*4, Kb + goff);
        cp16(sV_u + (row*VSTR + c*4)*4, Vb + goff);
    }
    CP_COMMIT();

    CP_WAIT1();            // Q group drained; first K/V may still be in flight
    __syncthreads();

    // ---- lift Q fragments (raw bits; already scaled+rounded by producer) ----
    uint32_t qa[8][4];
#pragma unroll
    for (int ks = 0; ks < 8; ks++) {
        const int col = ks*8 + t;
        qa[ks][0] = sP[(w*16 + g    )*KSTR + col];
        qa[ks][1] = sP[(w*16 + g + 8)*KSTR + col];
        qa[ks][2] = sP[(w*16 + g    )*KSTR + col + 4];
        qa[ks][3] = sP[(w*16 + g + 8)*KSTR + col + 4];
    }

    float m0 = -INFINITY, m1 = -INFINITY, l0 = 0.f, l1 = 0.f;
    float o[8][4];
#pragma unroll
    for (int db = 0; db < 8; db++)
#pragma unroll
        for (int j = 0; j < 4; j++) o[db][j] = 0.f;

    uint32_t* sPw = sP + (w*16)*KSTR;

    for (int it = 0; it < NITA; it++) {
        const int buf = it & 1;
        if (it + 1 < NITA) {
            const int nbuf = buf ^ 1;
#pragma unroll
            for (int i = 0; i < 4; i++) {
                int idx = tid + i*256, row = idx >> 4, c = idx & 15;
                size_t goff = (size_t)((it + 1)*KT + row)*INNER + c*4;
                cp16(sK_u + (nbuf*KT*KSTR + row*KSTR + c*4)*4, Kb + goff);
                cp16(sV_u + (nbuf*KT*VSTR + row*VSTR + c*4)*4, Vb + goff);
            }
            CP_COMMIT();
            CP_WAIT1();
        } else {
            CP_WAIT0();
        }
        __syncthreads();

        const uint32_t* tK = sK + buf*KT*KSTR;
        const uint32_t* tV = sV + buf*KT*VSTR;

        // ---- S = Q K^T (raw tf32 bits, no conversion) ----
        float s[8][4];
#pragma unroll
        for (int nb = 0; nb < 8; nb++)
#pragma unroll
            for (int j = 0; j < 4; j++) s[nb][j] = 0.f;

#pragma unroll
        for (int ks = 0; ks < 8; ks++) {
            const int col = ks*8 + t;
#pragma unroll
            for (int nb = 0; nb < 8; nb++) {
                uint32_t bfr[2];
                bfr[0] = tK[(nb*8 + g)*KSTR + col];
                bfr[1] = tK[(nb*8 + g)*KSTR + col + 4];
                mma_tf32(s[nb], qa[ks], bfr, s[nb]);
            }
        }

        // ---- online softmax in exp2 domain ----
        float rm0 = -INFINITY, rm1 = -INFINITY;
#pragma unroll
        for (int nb = 0; nb < 8; nb++) {
            rm0 = fmaxf(rm0, fmaxf(s[nb][0], s[nb][1]));
            rm1 = fmaxf(rm1, fmaxf(s[nb][2], s[nb][3]));
        }
        rm0 = fmaxf(rm0, __shfl_xor_sync(0xffffffffu, rm0, 1));
        rm0 = fmaxf(rm0, __shfl_xor_sync(0xffffffffu, rm0, 2));
        rm1 = fmaxf(rm1, __shfl_xor_sync(0xffffffffu, rm1, 1));
        rm1 = fmaxf(rm1, __shfl_xor_sync(0xffffffffu, rm1, 2));

        float mn0 = fmaxf(m0, rm0), mn1 = fmaxf(m1, rm1);
        float corr0 = ex2(m0 - mn0), corr1 = ex2(m1 - mn1);
        m0 = mn0; m1 = mn1;

        float rs0 = 0.f, rs1 = 0.f;
#pragma unroll
        for (int nb = 0; nb < 8; nb++) {
            s[nb][0] = ex2(s[nb][0] - m0);
            s[nb][1] = ex2(s[nb][1] - m0);
            s[nb][2] = ex2(s[nb][2] - m1);
            s[nb][3] = ex2(s[nb][3] - m1);
            rs0 += s[nb][0] + s[nb][1];
            rs1 += s[nb][2] + s[nb][3];
        }
        rs0 += __shfl_xor_sync(0xffffffffu, rs0, 1);
        rs0 += __shfl_xor_sync(0xffffffffu, rs0, 2);
        rs1 += __shfl_xor_sync(0xffffffffu, rs1, 1);
        rs1 += __shfl_xor_sync(0xffffffffu, rs1, 2);
        l0 = l0 * corr0 + rs0;
        l1 = l1 * corr1 + rs1;

#pragma unroll
        for (int db = 0; db < 8; db++) {
            o[db][0] *= corr0; o[db][1] *= corr0;
            o[db][2] *= corr1; o[db][3] *= corr1;
        }

        // ---- P -> smem (RNA tf32 once), re-read raw in A-layout ----
#pragma unroll
        for (int nb = 0; nb < 8; nb++) {
            sPw[(g    )*KSTR + nb*8 + 2*t    ] = f2tf32(s[nb][0]);
            sPw[(g    )*KSTR + nb*8 + 2*t + 1] = f2tf32(s[nb][1]);
            sPw[(g + 8)*KSTR + nb*8 + 2*t    ] = f2tf32(s[nb][2]);
            sPw[(g + 8)*KSTR + nb*8 + 2*t + 1] = f2tf32(s[nb][3]);
        }
        __syncwarp();

        // ---- O += P V (raw bits) ----
#pragma unroll
        for (int ks = 0; ks < 8; ks++) {
            uint32_t pa[4];
            pa[0] = sPw[(g    )*KSTR + ks*8 + t];
            pa[1] = sPw[(g + 8)*KSTR + ks*8 + t];
            pa[2] = sPw[(g    )*KSTR + ks*8 + t + 4];
            pa[3] = sPw[(g + 8)*KSTR + ks*8 + t + 4];
#pragma unroll
            for (int db = 0; db < 8; db++) {
                uint32_t bfr[2];
                bfr[0] = tV[(ks*8 + t    )*VSTR + db*8 + g];
                bfr[1] = tV[(ks*8 + t + 4)*VSTR + db*8 + g];
                mma_tf32(o[db], pa, bfr, o[db]);
            }
        }
        __syncthreads();
    }

    // ---- epilogue ----
    const float inv0 = 1.f / l0, inv1 = 1.f / l1;
    const int q0 = qt*BQ + w*16 + g, q1 = q0 + 8;
#pragma unroll
    for (int db = 0; db < 8; db++) {
        float2 r0 = make_float2(o[db][0]*inv0, o[db][1]*inv0);
        float2 r1 = make_float2(o[db][2]*inv1, o[db][3]*inv1);
        *(float2*)&g_AO[(size_t)(b*NQ + q0)*INNER + h*HD + db*8 + 2*t] = r0;
        *(float2*)&g_AO[(size_t)(b*NQ + q1)*INNER + h*HD + db*8 + 2*t] = r1;
    }
}

// ---------------------------------------------------------------------------
// Launch
// ---------------------------------------------------------------------------
extern "C" void kernel_launch(void* const* d_in, const int* in_sizes, int n_in,
                              void* d_out, int out_size)
{
    const float* q   = (const float*)d_in[0];
    const float* kv  = (const float*)d_in[1];
    const float* w_q = (const float*)d_in[2];
    const float* w_k = (const float*)d_in[3];
    const float* w_v = (const float*)d_in[4];
    const float* w_o = (const float*)d_in[5];
    const float* b_o = (const float*)d_in[6];
    float* out = (float*)d_out;

    float *Qp, *Kp, *Vp, *AO;
    cudaGetSymbolAddress((void**)&Qp, g_Qp);
    cudaGetSymbolAddress((void**)&Kp, g_Kp);
    cudaGetSymbolAddress((void**)&Vp, g_Vp);
    cudaGetSymbolAddress((void**)&AO, g_AO);

    const int MQ = BB * NQ;    // 8192
    const int MK = BB * NKV;   // 16384

    cudaFuncSetAttribute(gemm_tf32_kernel<false, true>,
                         cudaFuncAttributeMaxDynamicSharedMemorySize, GEMM_SMEM);
    cudaFuncSetAttribute(gemm_tf32_kernel<true, false>,
                         cudaFuncAttributeMaxDynamicSharedMemorySize, GEMM_SMEM);
    cudaFuncSetAttribute(attn_mma_kernel,
                         cudaFuncAttributeMaxDynamicSharedMemorySize, ATTN_SMEM);

    // Q projection: output pre-scaled by 0.125*log2(e) and tf32-rounded
    gemm_tf32_kernel<false, true><<<dim3(INNER/GBN, MQ/GBM), 256, GEMM_SMEM>>>(
        q, w_q, nullptr, Qp, MQ, INNER, QDIM, Q_PRESCALE);
    // K/V projections: tf32-rounded outputs
    gemm_tf32_kernel<false, true><<<dim3(INNER/GBN, MK/GBM), 256, GEMM_SMEM>>>(
        kv, w_k, nullptr, Kp, MK, INNER, KVDIM, 1.0f);
    gemm_tf32_kernel<false, true><<<dim3(INNER/GBN, MK/GBM), 256, GEMM_SMEM>>>(
        kv, w_v, nullptr, Vp, MK, INNER, KVDIM, 1.0f);

    attn_mma_kernel<<<dim3(NQ/BQ, NH, BB), 256, ATTN_SMEM>>>();

    // Output projection: full fp32 epilogue + bias
    gemm_tf32_kernel<true, false><<<dim3(QDIM/GBN, MQ/GBM), 256, GEMM_SMEM>>>(
        AO, w_o, b_o, out, MQ, QDIM, INNER, 1.0f);
}